// round 1
// baseline (speedup 1.0000x reference)
#include <cuda_runtime.h>
#include <cstdint>

// SparseBMM: C[b] = A[b] @ B[b]
//  A: [8, 4096, 4096] f32, ~80% of 128x128 tiles are exactly zero
//  B: [8, 4096, 128] f32
//  C: [8, 4096, 128] f32
//
// Strategy: one CTA per 64-row M-strip per batch (512 CTAs, all resident at
// 4 CTAs/SM). For each 64-wide K step, load the 64x64 A sub-tile to registers,
// block-OR a nonzero flag; skip B load + all math when the sub-tile is zero
// (~80% of steps). Nonzero steps use packed fma.rn.f32x2 (FFMA2) for 2x fp32
// FMA throughput with full fp32 accuracy.

#define BATCHES 8
#define MDIM    4096
#define KDIM    4096
#define NDIM    128
#define MT      64
#define KT      64
#define NTHREADS 128

#define AS_STRIDE (KT + 1)   // 65: avoids LDS bank conflicts on broadcast A reads
#define SMEM_FLOATS (MT * AS_STRIDE + KT * NDIM)
#define SMEM_BYTES  (SMEM_FLOATS * 4)

__global__ __launch_bounds__(NTHREADS, 4)
void sparse_bmm_kernel(const float* __restrict__ A,
                       const float* __restrict__ B,
                       float* __restrict__ C) {
    extern __shared__ float sm[];
    float* As = sm;                     // [MT][AS_STRIDE]
    float* Bs = sm + MT * AS_STRIDE;    // [KT][NDIM]

    const int bidx  = blockIdx.x;       // 0..511
    const int batch = bidx >> 6;        // 64 M-tiles per batch
    const int mt    = bidx & 63;

    const float* Ab = A + (size_t)batch * MDIM * KDIM + (size_t)mt * MT * KDIM;
    const float* Bb = B + (size_t)batch * KDIM * NDIM;
    float*       Cb = C + (size_t)batch * MDIM * NDIM + (size_t)mt * MT * NDIM;

    const int tid = threadIdx.x;
    const int tx  = tid & 15;   // column group: 8 output cols each
    const int ty  = tid >> 4;   // row group: 8 output rows each

    // 8 rows x 4 packed col-pairs = 8x8 fp32 outputs per thread
    unsigned long long acc[8][4];
#pragma unroll
    for (int i = 0; i < 8; i++)
#pragma unroll
        for (int p = 0; p < 4; p++) acc[i][p] = 0ull;

    for (int kt = 0; kt < KDIM / KT; kt++) {
        // ---- load 64x64 A sub-tile to registers, track nonzero ----
        float4 av[8];
        int nz = 0;
#pragma unroll
        for (int t = 0; t < 8; t++) {
            int idx = tid + t * NTHREADS;     // 0..1023 float4 slots
            int r = idx >> 4;                 // row 0..63
            int c = idx & 15;                 // float4 col 0..15
            av[t] = *(const float4*)(Ab + (size_t)r * KDIM + kt * KT + c * 4);
            nz |= (av[t].x != 0.0f) | (av[t].y != 0.0f) |
                  (av[t].z != 0.0f) | (av[t].w != 0.0f);
        }

        // Barrier doubles as the write-after-read guard for smem reuse:
        // no thread stores to smem below until every thread has finished
        // the previous step's compute.
        if (__syncthreads_or(nz)) {
            // ---- store A to smem (scalar, padded stride: conflict-free) ----
#pragma unroll
            for (int t = 0; t < 8; t++) {
                int idx = tid + t * NTHREADS;
                int r = idx >> 4;
                int c = (idx & 15) * 4;
                float* p = As + r * AS_STRIDE + c;
                p[0] = av[t].x; p[1] = av[t].y; p[2] = av[t].z; p[3] = av[t].w;
            }
            // ---- load 64x128 B tile (contiguous, L2-resident) ----
            const float4* Bg = (const float4*)(Bb + (size_t)kt * KT * NDIM);
            float4* Bs4 = (float4*)Bs;
#pragma unroll
            for (int t = 0; t < 16; t++)
                Bs4[tid + t * NTHREADS] = Bg[tid + t * NTHREADS];
            __syncthreads();

            // ---- compute: packed f32x2 FMAs ----
            const float* arow = As + (ty * 8) * AS_STRIDE;
#pragma unroll 8
            for (int kk = 0; kk < KT; kk++) {
                unsigned long long bb[4];
                const unsigned long long* bp =
                    (const unsigned long long*)(Bs + kk * NDIM + tx * 8);
#pragma unroll
                for (int p = 0; p < 4; p++) bb[p] = bp[p];

                unsigned long long aa[8];
#pragma unroll
                for (int i = 0; i < 8; i++) {
                    float a = arow[i * AS_STRIDE + kk];
                    asm("mov.b64 %0, {%1, %1};" : "=l"(aa[i]) : "f"(a));
                }
#pragma unroll
                for (int i = 0; i < 8; i++)
#pragma unroll
                    for (int p = 0; p < 4; p++)
                        asm("fma.rn.f32x2 %0, %1, %2, %0;"
                            : "+l"(acc[i][p])
                            : "l"(aa[i]), "l"(bb[p]));
            }
            // no trailing barrier needed: next iteration's __syncthreads_or
            // orders compute-done before the next smem overwrite
        }
    }

    // ---- epilogue: write all outputs (zeros included) ----
#pragma unroll
    for (int i = 0; i < 8; i++) {
        float* crow = Cb + (size_t)(ty * 8 + i) * NDIM + tx * 8;
#pragma unroll
        for (int p = 0; p < 4; p++)
            *(unsigned long long*)(crow + p * 2) = acc[i][p];
    }
}

extern "C" void kernel_launch(void* const* d_in, const int* in_sizes, int n_in,
                              void* d_out, int out_size) {
    const float* a = (const float*)d_in[0];
    const float* b = (const float*)d_in[1];
    float* c = (float*)d_out;

    cudaFuncSetAttribute(sparse_bmm_kernel,
                         cudaFuncAttributeMaxDynamicSharedMemorySize,
                         SMEM_BYTES);

    dim3 grid(BATCHES * (MDIM / MT));   // 512 CTAs
    sparse_bmm_kernel<<<grid, NTHREADS, SMEM_BYTES>>>(a, b, c);
}